// round 2
// baseline (speedup 1.0000x reference)
#include <cuda_runtime.h>
#include <cuda_bf16.h>

// Problem constants (max sizes for static scratch)
#define MAXN 100000
#define MAXE 1600000
#define C 128          // channel count for both aggregated feature matrices

// ---------------- static scratch (allocation-free rule) ----------------
__device__ int   g_cnt[MAXN];
__device__ int   g_fill[MAXN];
__device__ int   g_rowptr[MAXN + 1];
__device__ float g_dinv[MAXN];
__device__ int   g_srcs[MAXE];
__device__ float g_norms[MAXE];
__device__ float g_ax[(size_t)MAXN * C];   // agg(x)
__device__ float g_h [(size_t)MAXN * C];   // relu(agg(x)@W1+b1)
__device__ float g_ah[(size_t)MAXN * C];   // agg(h)
__device__ float g_W2[C * C];              // [Wmu | Wls] packed
__device__ float g_b2[C];

// ---------------- CSR build ----------------
__global__ void init_kernel(int n) {
    int i = blockIdx.x * blockDim.x + threadIdx.x;
    if (i < n) { g_cnt[i] = 0; g_fill[i] = 0; }
}

__global__ void count_kernel(const int* __restrict__ col, int e) {
    int i = blockIdx.x * blockDim.x + threadIdx.x;
    if (i < e) atomicAdd(&g_cnt[col[i]], 1);
}

// single-block exclusive scan over g_cnt -> g_rowptr
__global__ void scan_kernel(int n) {
    __shared__ int sums[1024];
    int t = threadIdx.x;
    int chunk = (n + 1023) / 1024;
    int start = t * chunk;
    int end = start + chunk; if (end > n) end = n; if (start > n) start = n;
    int s = 0;
    for (int i = start; i < end; i++) s += g_cnt[i];
    sums[t] = s;
    __syncthreads();
    for (int off = 1; off < 1024; off <<= 1) {
        int v = (t >= off) ? sums[t - off] : 0;
        __syncthreads();
        sums[t] += v;
        __syncthreads();
    }
    int run = (t == 0) ? 0 : sums[t - 1];
    for (int i = start; i < end; i++) { g_rowptr[i] = run; run += g_cnt[i]; }
    if (t == 1023) g_rowptr[n] = sums[1023];
}

__global__ void dinv_kernel(int n) {
    int i = blockIdx.x * blockDim.x + threadIdx.x;
    if (i < n) g_dinv[i] = rsqrtf((float)(g_cnt[i] + 1));  // +1 self loop
}

__global__ void scatter_kernel(const int* __restrict__ row,
                               const int* __restrict__ col, int e) {
    int i = blockIdx.x * blockDim.x + threadIdx.x;
    if (i < e) {
        int r = row[i], c = col[i];
        int p = g_rowptr[c] + atomicAdd(&g_fill[c], 1);
        g_srcs[p]  = r;
        g_norms[p] = g_dinv[r] * g_dinv[c];
    }
}

// ---------------- aggregation: warp per target node, 128 ch as float4/lane ----------
// PHASE 0: src = x (input param), dst = g_ax
// PHASE 1: src = g_h,            dst = g_ah
template <int PHASE>
__global__ void agg128_kernel(const float* __restrict__ xin, int n) {
    int w = (blockIdx.x * blockDim.x + threadIdx.x) >> 5;
    int lane = threadIdx.x & 31;
    if (w >= n) return;
    const float4* s4 = (PHASE == 0) ? (const float4*)xin : (const float4*)g_h;
    float4* d4       = (PHASE == 0) ? (float4*)g_ax      : (float4*)g_ah;

    float di = g_dinv[w];
    float sw = di * di;
    float4 a = s4[(size_t)w * 32 + lane];
    float4 acc = make_float4(a.x * sw, a.y * sw, a.z * sw, a.w * sw);

    int p = g_rowptr[w];
    int end = g_rowptr[w + 1];
    int   s_next = 0; float w_next = 0.f;
    if (p < end) { s_next = g_srcs[p]; w_next = g_norms[p]; }
    while (p < end) {
        int s = s_next; float wt = w_next;
        if (p + 1 < end) { s_next = g_srcs[p + 1]; w_next = g_norms[p + 1]; }
        float4 v = s4[(size_t)s * 32 + lane];
        acc.x += wt * v.x; acc.y += wt * v.y;
        acc.z += wt * v.z; acc.w += wt * v.w;
        p++;
    }
    d4[(size_t)w * 32 + lane] = acc;
}

// ---------------- GEMM: C[n,128] = A[n,128] @ W[128,128] + bias ----------
// MODE 0: A = g_ax, W/bias = params (W1,b1), relu, store g_h
// MODE 1: A = g_ah, W = g_W2, bias = g_b2, split cols -> out0 (mu), out1 (logstd)
template <int MODE>
__global__ void gemm128_kernel(const float* __restrict__ Wp, const float* __restrict__ bp,
                               float* __restrict__ out0, float* __restrict__ out1, int n) {
    __shared__ float Wt[64 * 128];  // 32 KB: one K-tile of W
    __shared__ float Xt[64 * 64];   // 16 KB: 64 rows x 64 k
    const float* A    = (MODE == 0) ? g_ax : g_ah;
    const float* W    = (MODE == 0) ? Wp : g_W2;
    const float* bias = (MODE == 0) ? bp : g_b2;

    int warp = threadIdx.x >> 5;
    int lane = threadIdx.x & 31;
    int row0 = blockIdx.x * 64;

    float4 acc[8];
#pragma unroll
    for (int r = 0; r < 8; r++) acc[r] = make_float4(0.f, 0.f, 0.f, 0.f);

    for (int kt = 0; kt < 2; kt++) {
        // load W tile: W[(kt*64+kk)*128 + j]
        for (int i = threadIdx.x; i < 64 * 32; i += 256) {
            ((float4*)Wt)[i] = ((const float4*)W)[(kt * 64 + (i >> 5)) * 32 + (i & 31)];
        }
        // load X tile: rows row0..row0+63, k in [kt*64, kt*64+64)
        for (int i = threadIdx.x; i < 64 * 16; i += 256) {
            int rr = i >> 4, kq = i & 15;
            int r = row0 + rr;
            float4 v = make_float4(0.f, 0.f, 0.f, 0.f);
            if (r < n) v = ((const float4*)A)[(size_t)r * 32 + kt * 16 + kq];
            ((float4*)Xt)[i] = v;
        }
        __syncthreads();
#pragma unroll 8
        for (int kk = 0; kk < 64; kk++) {
            float4 w4 = ((const float4*)Wt)[kk * 32 + lane];
#pragma unroll
            for (int rr = 0; rr < 8; rr++) {
                float xv = Xt[(warp * 8 + rr) * 64 + kk];
                acc[rr].x += xv * w4.x;
                acc[rr].y += xv * w4.y;
                acc[rr].z += xv * w4.z;
                acc[rr].w += xv * w4.w;
            }
        }
        __syncthreads();
    }

    float4 b4 = ((const float4*)bias)[lane];
#pragma unroll
    for (int rr = 0; rr < 8; rr++) {
        int row = row0 + warp * 8 + rr;
        if (row >= n) continue;
        float4 v = acc[rr];
        v.x += b4.x; v.y += b4.y; v.z += b4.z; v.w += b4.w;
        if (MODE == 0) {
            v.x = fmaxf(v.x, 0.f); v.y = fmaxf(v.y, 0.f);
            v.z = fmaxf(v.z, 0.f); v.w = fmaxf(v.w, 0.f);
            ((float4*)g_h)[(size_t)row * 32 + lane] = v;
        } else {
            if (lane < 16)
                ((float4*)out0)[(size_t)row * 16 + lane] = v;        // mu
            else
                ((float4*)out1)[(size_t)row * 16 + (lane - 16)] = v; // logstd
        }
    }
}

// pack W2 = [Wmu | Wls], b2 = [bmu | bls]
__global__ void pack_w2_kernel(const float* __restrict__ Wmu, const float* __restrict__ bmu,
                               const float* __restrict__ Wls, const float* __restrict__ bls) {
    int j = threadIdx.x;   // 128
    int k = blockIdx.x;    // 128
    g_W2[k * 128 + j] = (j < 64) ? Wmu[k * 64 + j] : Wls[k * 64 + (j - 64)];
    if (k == 0) g_b2[j] = (j < 64) ? bmu[j] : bls[j - 64];
}

// ---------------- launch ----------------
extern "C" void kernel_launch(void* const* d_in, const int* in_sizes, int n_in,
                              void* d_out, int out_size) {
    const float* x   = (const float*)d_in[0];
    const int*   ei  = (const int*)d_in[1];
    const float* W1  = (const float*)d_in[3];
    const float* b1  = (const float*)d_in[4];
    const float* Wmu = (const float*)d_in[5];
    const float* bmu = (const float*)d_in[6];
    const float* Wls = (const float*)d_in[7];
    const float* bls = (const float*)d_in[8];
    float* out = (float*)d_out;

    int n = in_sizes[0] / C;       // 100000
    int e = in_sizes[1] / 2;       // 1600000
    const int* erow = ei;
    const int* ecol = ei + e;

    float* mu = out;
    float* ls = out + (size_t)n * 64;

    int nb_n = (n + 255) / 256;
    int nb_e = (e + 255) / 256;

    // CSR build (once per launch; inputs identical every replay)
    init_kernel<<<nb_n, 256>>>(n);
    count_kernel<<<nb_e, 256>>>(ecol, e);
    scan_kernel<<<1, 1024>>>(n);
    dinv_kernel<<<nb_n, 256>>>(n);
    scatter_kernel<<<nb_e, 256>>>(erow, ecol, e);
    pack_w2_kernel<<<128, 128>>>(Wmu, bmu, Wls, bls);

    int agg_blocks = (n + 7) / 8;          // 8 warps/block, warp per node
    int gemm_blocks = (n + 63) / 64;

    // layer 1: h = relu(agg(x) @ W1 + b1)
    agg128_kernel<0><<<agg_blocks, 256>>>(x, n);
    gemm128_kernel<0><<<gemm_blocks, 256>>>(W1, b1, nullptr, nullptr, n);

    // layers 2+3 share one aggregation: ah = agg(h); mu/ls = ah @ [Wmu|Wls] + [bmu|bls]
    agg128_kernel<1><<<agg_blocks, 256>>>(nullptr, n);
    gemm128_kernel<1><<<gemm_blocks, 256>>>(nullptr, nullptr, mu, ls, n);
}